// round 5
// baseline (speedup 1.0000x reference)
#include <cuda_runtime.h>
#include <cuda_bf16.h>
#include <stdint.h>

#define N_NODES  100000
#define N_EDGES  1600000
#define IN_C     128
#define HID      128
#define LAT      64
#define N_LAYERS 3
#define N_GRAPHS 1000

#define SCAN_B   512
#define SCAN_NB  ((N_NODES + SCAN_B - 1) / SCAN_B)   // 196

// ---------------- scratch (device globals; no allocation allowed) ----------------
__device__ __align__(16) float g_bufA[N_NODES * HID];
__device__ __align__(16) float g_bufB[N_NODES * HID];
__device__ __align__(16) float g_pool[N_GRAPHS * HID];
__device__ int   g_deg[N_NODES];
__device__ int   g_rowptr[N_NODES + 1];
__device__ int   g_cursor[N_NODES];
__device__ int   g_col[N_EDGES];
__device__ int   g_bsums[SCAN_NB];
__device__ int   g_is64;   // 1 if indices are int64 on device, 0 if int32

// index loader that works for either int32 or int64 device layout
__device__ __forceinline__ int idx_at(const void* p, long long i, int is64) {
    if (is64) return (int)((const long long*)p)[i];
    return ((const int*)p)[i];
}

// ---------------- dtype detection (runs in-graph, deterministic) ----------------
__global__ void k_detect(const void* ei) {
    if (threadIdx.x == 0 && blockIdx.x == 0) {
        const long long* e64 = (const long long*)ei;
        int ok = 1;
        for (int i = 0; i < 256; i++) {
            long long v = e64[i];
            if (v < 0 || v >= N_NODES) { ok = 0; break; }
        }
        g_is64 = ok;
    }
}

// ---------------- init / CSR build ----------------
__global__ void k_zero() {
    int i = blockIdx.x * blockDim.x + threadIdx.x;
    if (i < N_NODES) g_deg[i] = 0;
    if (i < N_GRAPHS * HID) g_pool[i] = 0.0f;
}

__global__ void k_hist(const void* __restrict__ ei) {
    int e = blockIdx.x * blockDim.x + threadIdx.x;
    int is64 = g_is64;
    if (e < N_EDGES) {
        int dst = idx_at(ei, (long long)N_EDGES + e, is64);
        atomicAdd(&g_deg[dst], 1);
    }
}

__global__ void k_scan_local() {
    __shared__ int s[SCAN_B];
    int i = blockIdx.x * SCAN_B + threadIdx.x;
    int v = (i < N_NODES) ? g_deg[i] : 0;
    s[threadIdx.x] = v;
    __syncthreads();
    #pragma unroll
    for (int off = 1; off < SCAN_B; off <<= 1) {
        int t = (threadIdx.x >= off) ? s[threadIdx.x - off] : 0;
        __syncthreads();
        s[threadIdx.x] += t;
        __syncthreads();
    }
    if (i < N_NODES) g_rowptr[i] = s[threadIdx.x] - v;   // exclusive prefix
    if (threadIdx.x == SCAN_B - 1) g_bsums[blockIdx.x] = s[threadIdx.x];
}

__global__ void k_scan_bsums() {
    if (threadIdx.x == 0 && blockIdx.x == 0) {
        int acc = 0;
        for (int b = 0; b < SCAN_NB; b++) { int t = g_bsums[b]; g_bsums[b] = acc; acc += t; }
    }
}

__global__ void k_scan_add() {
    int i = blockIdx.x * SCAN_B + threadIdx.x;
    if (i < N_NODES) {
        int v = g_rowptr[i] + g_bsums[blockIdx.x];
        g_rowptr[i] = v;
        g_cursor[i] = v;
    }
    if (i == 0) g_rowptr[N_NODES] = N_EDGES;
}

__global__ void k_scatter(const void* __restrict__ ei) {
    int e = blockIdx.x * blockDim.x + threadIdx.x;
    int is64 = g_is64;
    if (e < N_EDGES) {
        int src = idx_at(ei, e, is64);
        int dst = idx_at(ei, (long long)N_EDGES + e, is64);
        int pos = atomicAdd(&g_cursor[dst], 1);
        g_col[pos] = src;
    }
}

// ---------------- aggregation: agg[n] = h[n] + sum_{e in CSR(n)} h[col[e]] ----------------
// warp per node; lane owns one float4 (4 features)
__global__ __launch_bounds__(256) void k_agg(const float* __restrict__ h,
                                             float* __restrict__ out) {
    int warp = (blockIdx.x * blockDim.x + threadIdx.x) >> 5;
    int lane = threadIdx.x & 31;
    if (warp >= N_NODES) return;
    const float4* h4 = (const float4*)h;
    float4 acc = h4[(size_t)warp * 32 + lane];
    int s = g_rowptr[warp];
    int e = g_rowptr[warp + 1];
    int j = s;
    for (; j + 1 < e; j += 2) {
        int s0 = g_col[j];
        int s1 = g_col[j + 1];
        float4 v0 = h4[(size_t)s0 * 32 + lane];
        float4 v1 = h4[(size_t)s1 * 32 + lane];
        acc.x += v0.x + v1.x; acc.y += v0.y + v1.y;
        acc.z += v0.z + v1.z; acc.w += v0.w + v1.w;
    }
    if (j < e) {
        int s0 = g_col[j];
        float4 v0 = h4[(size_t)s0 * 32 + lane];
        acc.x += v0.x; acc.y += v0.y; acc.z += v0.z; acc.w += v0.w;
    }
    ((float4*)out)[(size_t)warp * 32 + lane] = acc;
}

// ---------------- GEMM + bias + ReLU:  C[M,128] = relu(A[M,128] @ W[128,128] + b) --------
// block: 64 rows x 128 cols, 256 threads, thread tile 4 rows x 8 cols, K chunked by 32
__global__ __launch_bounds__(256) void k_gemm_relu(const float* __restrict__ A,
                                                   const float* __restrict__ W,
                                                   const float* __restrict__ bias,
                                                   float* __restrict__ C) {
    __shared__ float As[64][33];
    __shared__ float Ws[32][128];
    int tid = threadIdx.x;
    int cg = tid & 15;    // col group: cols cg*8 .. cg*8+7
    int rg = tid >> 4;    // row group: rows rg*4 .. rg*4+3
    int rowBase = blockIdx.x * 64;

    float acc[4][8];
    #pragma unroll
    for (int r = 0; r < 4; r++)
        #pragma unroll
        for (int c = 0; c < 8; c++) acc[r][c] = 0.0f;

    for (int kk = 0; kk < 128; kk += 32) {
        // load A tile: 64x32
        #pragma unroll
        for (int i = 0; i < 8; i++) {
            int idx = tid + i * 256;            // 0..2047
            int r = idx >> 5, k = idx & 31;
            int row = rowBase + r;
            As[r][k] = (row < N_NODES) ? A[(size_t)row * 128 + kk + k] : 0.0f;
        }
        // load W tile: 32x128 (float4)
        #pragma unroll
        for (int i = 0; i < 4; i++) {
            int idx = tid + i * 256;            // 0..1023 float4s
            int k = idx >> 5;
            int c4 = idx & 31;
            ((float4*)&Ws[k][0])[c4] = ((const float4*)W)[(size_t)(kk + k) * 32 + c4];
        }
        __syncthreads();
        #pragma unroll
        for (int k = 0; k < 32; k++) {
            float a0 = As[rg * 4 + 0][k];
            float a1 = As[rg * 4 + 1][k];
            float a2 = As[rg * 4 + 2][k];
            float a3 = As[rg * 4 + 3][k];
            float4 w0 = *(const float4*)&Ws[k][cg * 8];
            float4 w1 = *(const float4*)&Ws[k][cg * 8 + 4];
            acc[0][0] += a0 * w0.x; acc[0][1] += a0 * w0.y; acc[0][2] += a0 * w0.z; acc[0][3] += a0 * w0.w;
            acc[0][4] += a0 * w1.x; acc[0][5] += a0 * w1.y; acc[0][6] += a0 * w1.z; acc[0][7] += a0 * w1.w;
            acc[1][0] += a1 * w0.x; acc[1][1] += a1 * w0.y; acc[1][2] += a1 * w0.z; acc[1][3] += a1 * w0.w;
            acc[1][4] += a1 * w1.x; acc[1][5] += a1 * w1.y; acc[1][6] += a1 * w1.z; acc[1][7] += a1 * w1.w;
            acc[2][0] += a2 * w0.x; acc[2][1] += a2 * w0.y; acc[2][2] += a2 * w0.z; acc[2][3] += a2 * w0.w;
            acc[2][4] += a2 * w1.x; acc[2][5] += a2 * w1.y; acc[2][6] += a2 * w1.z; acc[2][7] += a2 * w1.w;
            acc[3][0] += a3 * w0.x; acc[3][1] += a3 * w0.y; acc[3][2] += a3 * w0.z; acc[3][3] += a3 * w0.w;
            acc[3][4] += a3 * w1.x; acc[3][5] += a3 * w1.y; acc[3][6] += a3 * w1.z; acc[3][7] += a3 * w1.w;
        }
        __syncthreads();
    }

    float b[8];
    #pragma unroll
    for (int c = 0; c < 8; c++) b[c] = bias[cg * 8 + c];

    #pragma unroll
    for (int r = 0; r < 4; r++) {
        int row = rowBase + rg * 4 + r;
        if (row < N_NODES) {
            float4 o0, o1;
            o0.x = fmaxf(acc[r][0] + b[0], 0.0f);
            o0.y = fmaxf(acc[r][1] + b[1], 0.0f);
            o0.z = fmaxf(acc[r][2] + b[2], 0.0f);
            o0.w = fmaxf(acc[r][3] + b[3], 0.0f);
            o1.x = fmaxf(acc[r][4] + b[4], 0.0f);
            o1.y = fmaxf(acc[r][5] + b[5], 0.0f);
            o1.z = fmaxf(acc[r][6] + b[6], 0.0f);
            o1.w = fmaxf(acc[r][7] + b[7], 0.0f);
            float4* cp = (float4*)&C[(size_t)row * 128 + cg * 8];
            cp[0] = o0;
            cp[1] = o1;
        }
    }
}

// ---------------- global add pool: pool[batch[n]] += h[n] ----------------
__global__ __launch_bounds__(256) void k_pool(const float* __restrict__ h,
                                              const void* __restrict__ batch) {
    int warp = (blockIdx.x * blockDim.x + threadIdx.x) >> 5;
    int lane = threadIdx.x & 31;
    if (warp >= N_NODES) return;
    int gidx = idx_at(batch, warp, g_is64);
    float4 v = ((const float4*)h)[(size_t)warp * 32 + lane];
    float* base = &g_pool[(size_t)gidx * 128 + lane * 4];
    atomicAdd(base + 0, v.x);
    atomicAdd(base + 1, v.y);
    atomicAdd(base + 2, v.z);
    atomicAdd(base + 3, v.w);
}

// ---------------- head: mu = g@W_mu+b_mu, lv = g@W_lv+b_lv ----------------
__global__ __launch_bounds__(128) void k_head(const float* __restrict__ Wmu,
                                              const float* __restrict__ bmu,
                                              const float* __restrict__ Wlv,
                                              const float* __restrict__ blv,
                                              float* __restrict__ out) {
    __shared__ float p[128];
    int g = blockIdx.x;
    p[threadIdx.x] = g_pool[(size_t)g * 128 + threadIdx.x];
    __syncthreads();
    int t = threadIdx.x;
    const float* W = (t < 64) ? Wmu : Wlv;
    const float* b = (t < 64) ? bmu : blv;
    int c = t & 63;
    float acc = 0.0f;
    #pragma unroll 8
    for (int k = 0; k < 128; k++) acc += p[k] * W[k * 64 + c];
    acc += b[c];
    size_t off = (t < 64) ? 0 : (size_t)N_GRAPHS * LAT;
    out[off + (size_t)g * 64 + c] = acc;
}

// ---------------- launch ----------------
extern "C" void kernel_launch(void* const* d_in, const int* in_sizes, int n_in,
                              void* d_out, int out_size) {
    const float* x    = (const float*)d_in[0];
    const void*  ei   = d_in[1];           // int32 or int64; detected in-graph
    const void*  bat  = d_in[2];
    const float* W1   = (const float*)d_in[3];
    const float* b1   = (const float*)d_in[4];
    const float* W2   = (const float*)d_in[5];
    const float* b2   = (const float*)d_in[6];
    const float* Wmu  = (const float*)d_in[7];
    const float* bmu  = (const float*)d_in[8];
    const float* Wlv  = (const float*)d_in[9];
    const float* blv  = (const float*)d_in[10];
    float*       out  = (float*)d_out;

    float *bufA, *bufB;
    cudaGetSymbolAddress((void**)&bufA, g_bufA);
    cudaGetSymbolAddress((void**)&bufB, g_bufB);

    // dtype detect + init + CSR build (per-launch; replay-safe)
    k_detect<<<1, 32>>>(ei);
    k_zero<<<(N_GRAPHS * HID + 255) / 256, 256>>>();
    k_hist<<<(N_EDGES + 255) / 256, 256>>>(ei);
    k_scan_local<<<SCAN_NB, SCAN_B>>>();
    k_scan_bsums<<<1, 32>>>();
    k_scan_add<<<SCAN_NB, SCAN_B>>>();
    k_scatter<<<(N_EDGES + 255) / 256, 256>>>(ei);

    const int aggGrid  = (N_NODES * 32 + 255) / 256;   // warp per node
    const int gemmGrid = (N_NODES + 63) / 64;

    // layer 0: x -> A -> B -> A
    k_agg<<<aggGrid, 256>>>(x, bufA);
    k_gemm_relu<<<gemmGrid, 256>>>(bufA, W1 + 0 * 128 * 128, b1 + 0 * 128, bufB);
    k_gemm_relu<<<gemmGrid, 256>>>(bufB, W2 + 0 * 128 * 128, b2 + 0 * 128, bufA);
    // layer 1
    k_agg<<<aggGrid, 256>>>(bufA, bufB);
    k_gemm_relu<<<gemmGrid, 256>>>(bufB, W1 + 1 * 128 * 128, b1 + 1 * 128, bufA);
    k_gemm_relu<<<gemmGrid, 256>>>(bufA, W2 + 1 * 128 * 128, b2 + 1 * 128, bufB);
    // layer 2
    k_agg<<<aggGrid, 256>>>(bufB, bufA);
    k_gemm_relu<<<gemmGrid, 256>>>(bufA, W1 + 2 * 128 * 128, b1 + 2 * 128, bufB);
    k_gemm_relu<<<gemmGrid, 256>>>(bufB, W2 + 2 * 128 * 128, b2 + 2 * 128, bufA);

    // pool + heads
    k_pool<<<aggGrid, 256>>>(bufA, bat);
    k_head<<<N_GRAPHS, 128>>>(Wmu, bmu, Wlv, blv, out);
}